// round 14
// baseline (speedup 1.0000x reference)
#include <cuda_runtime.h>

typedef unsigned long long u64;

// Problem constants
#define B 1024
#define T 30
#define M 20
#define TWO_T (2*T)
#define BLOCK_ELEMS (TWO_T*TWO_T)   // 3600 floats per (b,m) chol block
#define BLOCK_F4    (BLOCK_ELEMS/4) // 900 float4

// Output layout (concatenated fp32, reference tuple order)
#define N_PROBS_TRAJ   (B*M)
#define N_LOC          (B*M*TWO_T)
#define N_CHOL_FULL    (B*M*TWO_T*TWO_T)
#define N_STEP_PROBS   (B*T*M)
#define N_MU           (B*T*M*2)
#define N_CHOL_STEP    (B*T*M*4)

#define O_PROBS_TRAJ   0
#define O_LOC          (O_PROBS_TRAJ + N_PROBS_TRAJ)   // 20480
#define O_CHOL_FULL    (O_LOC + N_LOC)                 // 1249280
#define O_STEP_PROBS   (O_CHOL_FULL + N_CHOL_FULL)     // 74977280
#define O_MU           (O_STEP_PROBS + N_STEP_PROBS)   // 75591680
#define O_CHOL_STEP    (O_MU + N_MU)                   // 76820480

#define VAR_EPS 1e-6f
#define PRUNE_DELTA 0.02f
#define PRUNE_TAU   0.1f
#define PRUNE_EPS   1e-8f

#define TILES_TOTAL   (B*M)                         // 20480
#define TILES_PER_CTA 8
#define CHOL_CTAS     (TILES_TOTAL / TILES_PER_CTA) // 2560

// First KEEP_CTAS chol CTAs (768*8 = 6144 tiles = 88.5 MB) use
// L2 evict_last (via cache_hint policy) so those lines persist across
// graph replays and never reach DRAM in steady state.
#define KEEP_CTAS     768

#define SM_ROWS       (B + B*T)                     // 31744 softmax rows total
#define SM_CTAS       (SM_ROWS / 256)               // 124 (exact)
#define GRID_TOTAL    (SM_CTAS + CHOL_CTAS)         // 2684

// smem: per tile k, 60 float4 rows of baked diagonal values
#define ROWS_PER_TILE 60

__device__ __forceinline__ u64 make_evict_last_policy() {
    u64 pol;
    asm("createpolicy.fractional.L2::evict_last.b64 %0, 1.0;" : "=l"(pol));
    return pol;
}

__device__ __forceinline__ void st_f4_hint(float4* p, float4 v, u64 pol) {
    asm volatile("st.global.L2::cache_hint.v4.f32 [%0], {%1, %2, %3, %4}, %5;"
                 :: "l"(p), "f"(v.x), "f"(v.y), "f"(v.z), "f"(v.w), "l"(pol)
                 : "memory");
}

// ---------------------------------------------------------------------------
__global__ void __launch_bounds__(256, 6) mdn_fused(
    const float* __restrict__ ml,     // [B, T, M*5]
    const float* __restrict__ trajw,  // [B, M]
    const float* __restrict__ stepw,  // [B, T*M]
    float* __restrict__ out) {

    __shared__ float4 DiagVal[TILES_PER_CTA * ROWS_PER_TILE];

    int bid = blockIdx.x;
    int tid = threadIdx.x;

    if (bid < SM_CTAS) {
        // ---------------- pruned softmax path ----------------
        // softmax(log(p_new + eps)) == (p_new + eps)/sum(p_new + eps)
        int r = bid * 256 + tid;          // [0, 31744)
        const float* x;
        float* o;
        if (r < B) {
            x = trajw + (size_t)r * M;
            o = out + O_PROBS_TRAJ + (size_t)r * M;
        } else {
            int rr = r - B;
            x = stepw + (size_t)rr * M;
            o = out + O_STEP_PROBS + (size_t)rr * M;
        }
        float v[M];
        const float4* x4 = reinterpret_cast<const float4*>(x);
        #pragma unroll
        for (int q = 0; q < M / 4; q++) {
            float4 f = x4[q];
            v[4*q] = f.x; v[4*q+1] = f.y; v[4*q+2] = f.z; v[4*q+3] = f.w;
        }
        float mx = v[0];
        #pragma unroll
        for (int j = 1; j < M; j++) mx = fmaxf(mx, v[j]);
        float s = 0.f;
        #pragma unroll
        for (int j = 0; j < M; j++) { v[j] = __expf(v[j] - mx); s += v[j]; }
        float inv_s = 1.0f / s;
        float s2 = 0.f;
        #pragma unroll
        for (int j = 0; j < M; j++) {
            float pj   = v[j] * inv_s;
            float gate = 1.0f / (1.0f + __expf(-(pj - PRUNE_DELTA) / PRUNE_TAU));
            float pt   = pj * gate;
            v[j] = pt;
            s2 += pt;
        }
        float inv_s2 = 1.0f / (s2 + PRUNE_EPS);
        float s3 = 0.f;
        #pragma unroll
        for (int j = 0; j < M; j++) {
            float pn = v[j] * inv_s2 + PRUNE_EPS;
            v[j] = pn;
            s3 += pn;
        }
        float inv_s3 = 1.0f / s3;
        float4* o4 = reinterpret_cast<float4*>(o);
        #pragma unroll
        for (int q = 0; q < M / 4; q++)
            o4[q] = make_float4(v[4*q] * inv_s3, v[4*q+1] * inv_s3,
                                v[4*q+2] * inv_s3, v[4*q+3] * inv_s3);
        return;
    }

    // ---------------- chol + dense path ----------------
    int cbid  = bid - SM_CTAS;
    int tile0 = cbid * TILES_PER_CTA;
    bool keep = (cbid < KEEP_CTAS);    // uniform per CTA

    // Phase 1: threads 0..239 -> (t = tid>>3, k = tid&7); compute params,
    // write mu / chol_step / loc, and bake the diag float4s into smem.
    if (tid < TILES_PER_CTA * T) {
        int k = tid & 7;
        int t = tid >> 3;
        int tl = tile0 + k;            // tl = b*M + m
        int m = tl % M;
        int b = tl / M;
        int i = (b * T + t) * M + m;   // dense index (b,t,m)

        const float* p = ml + (size_t)i * 5;
        float mu_x = p[0];
        float mu_y = p[1];
        float sx   = sqrtf(expf(p[2]) + VAR_EPS);
        float sy   = sqrtf(expf(p[3]) + VAR_EPS);
        float rho  = tanhf(p[4]);

        float L11 = sx;
        float L21 = rho * sy;
        float L22 = sy * sqrtf(fmaxf(1.0f - rho * rho, 0.0f));

        // lane placement: diag col 2t occupies f4 lanes (2t&3, (2t&3)+1)
        bool hi = (t & 1);             // t odd -> values in .z/.w
        float4 ev = hi ? make_float4(0.f, 0.f, L11, 0.f)
                       : make_float4(L11, 0.f, 0.f, 0.f);
        float4 od = hi ? make_float4(0.f, 0.f, L21, L22)
                       : make_float4(L21, L22, 0.f, 0.f);
        DiagVal[k * ROWS_PER_TILE + 2 * t]     = ev;
        DiagVal[k * ROWS_PER_TILE + 2 * t + 1] = od;

        // mu [B,T,M,2]
        *reinterpret_cast<float2*>(out + O_MU + (size_t)i * 2) =
            make_float2(mu_x, mu_y);
        // chol_step [B,T,M,2,2] = [L11, 0, L21, L22]
        *reinterpret_cast<float4*>(out + O_CHOL_STEP + (size_t)i * 4) =
            make_float4(L11, 0.0f, L21, L22);
        // loc [B,M,2T]
        *reinterpret_cast<float2*>(out + O_LOC + (size_t)tl * TWO_T + 2 * t) =
            make_float2(mu_x, mu_y);
    }
    __syncthreads();

    // Phase 2: each thread owns f4 slots q = tid + 256*s, s in [0,4).
    // Diag slots (rare, tile-invariant) read baked values from smem; all
    // other slots store a constant-zero register directly.
    int  s_idx[4];      // smem row index within a tile block (diag only)
    bool s_diag[4];
    bool s_on[4];
    #pragma unroll
    for (int s = 0; s < 4; s++) {
        int q = tid + 256 * s;
        s_on[s] = (q < BLOCK_F4);
        int r  = q / 15;
        int c4 = q % 15;
        int t  = r >> 1;
        s_diag[s] = s_on[s] && (c4 == (t >> 1)) && (t < T);
        s_idx[s] = s_diag[s] ? r : 0;
    }

    float4* dst = reinterpret_cast<float4*>(out + O_CHOL_FULL) +
                  (size_t)tile0 * BLOCK_F4 + tid;
    const float4* diag_base = DiagVal;
    const float4 z4 = make_float4(0.f, 0.f, 0.f, 0.f);

    if (keep) {
        // L2-resident slice: evict_last policy so lines persist across replays
        u64 pol = make_evict_last_policy();
        #pragma unroll
        for (int k = 0; k < TILES_PER_CTA; k++) {
            #pragma unroll
            for (int s = 0; s < 4; s++) {
                if (s_on[s]) {
                    float4 v = z4;
                    if (s_diag[s]) v = diag_base[s_idx[s]];
                    st_f4_hint(dst + 256 * s, v, pol);
                }
            }
            diag_base += ROWS_PER_TILE;
            dst += BLOCK_F4;
        }
    } else {
        // streaming slice: evict_first, drain to DRAM
        #pragma unroll
        for (int k = 0; k < TILES_PER_CTA; k++) {
            #pragma unroll
            for (int s = 0; s < 4; s++) {
                if (s_on[s]) {
                    float4 v = z4;
                    if (s_diag[s]) v = diag_base[s_idx[s]];
                    __stcs(dst + 256 * s, v);
                }
            }
            diag_base += ROWS_PER_TILE;
            dst += BLOCK_F4;
        }
    }
}

// ---------------------------------------------------------------------------
extern "C" void kernel_launch(void* const* d_in, const int* in_sizes, int n_in,
                              void* d_out, int out_size) {
    const float* ml    = (const float*)d_in[0];  // mixture_latent
    const float* trajw = (const float*)d_in[1];  // per_traj_weight
    const float* stepw = (const float*)d_in[2];  // per_step_weight
    float* out = (float*)d_out;

    mdn_fused<<<GRID_TOTAL, 256>>>(ml, trajw, stepw, out);
}

// round 16
// speedup vs baseline: 1.2330x; 1.2330x over previous
#include <cuda_runtime.h>

// Problem constants
#define B 1024
#define T 30
#define M 20
#define TWO_T (2*T)
#define BLOCK_ELEMS (TWO_T*TWO_T)   // 3600 floats per (b,m) chol block
#define BLOCK_F4    (BLOCK_ELEMS/4) // 900 float4

// Output layout (concatenated fp32, reference tuple order)
#define N_PROBS_TRAJ   (B*M)
#define N_LOC          (B*M*TWO_T)
#define N_CHOL_FULL    (B*M*TWO_T*TWO_T)
#define N_STEP_PROBS   (B*T*M)
#define N_MU           (B*T*M*2)
#define N_CHOL_STEP    (B*T*M*4)

#define O_PROBS_TRAJ   0
#define O_LOC          (O_PROBS_TRAJ + N_PROBS_TRAJ)   // 20480
#define O_CHOL_FULL    (O_LOC + N_LOC)                 // 1249280
#define O_STEP_PROBS   (O_CHOL_FULL + N_CHOL_FULL)     // 74977280
#define O_MU           (O_STEP_PROBS + N_STEP_PROBS)   // 75591680
#define O_CHOL_STEP    (O_MU + N_MU)                   // 76820480

#define VAR_EPS 1e-6f
#define PRUNE_DELTA 0.02f
#define PRUNE_TAU   0.1f
#define PRUNE_EPS   1e-8f

#define TILES_TOTAL   (B*M)                         // 20480
#define TILES_PER_CTA 2
#define CHOL_CTAS     (TILES_TOTAL / TILES_PER_CTA) // 10240

#define SM_ROWS       (B + B*T)                     // 31744 softmax rows total
#define SM_CTAS       (SM_ROWS / 256)               // 124 (exact)
#define GRID_TOTAL    (SM_CTAS + CHOL_CTAS)         // 10364

// smem: per tile k, 60 float4 rows of baked diagonal values
#define ROWS_PER_TILE 60

// ---------------------------------------------------------------------------
__global__ void __launch_bounds__(256, 6) mdn_fused(
    const float* __restrict__ ml,     // [B, T, M*5]
    const float* __restrict__ trajw,  // [B, M]
    const float* __restrict__ stepw,  // [B, T*M]
    float* __restrict__ out) {

    __shared__ float4 DiagVal[TILES_PER_CTA * ROWS_PER_TILE];

    int bid = blockIdx.x;
    int tid = threadIdx.x;

    if (bid < SM_CTAS) {
        // ---------------- pruned softmax path ----------------
        // softmax(log(p_new + eps)) == (p_new + eps)/sum(p_new + eps)
        int r = bid * 256 + tid;          // [0, 31744)
        const float* x;
        float* o;
        if (r < B) {
            x = trajw + (size_t)r * M;
            o = out + O_PROBS_TRAJ + (size_t)r * M;
        } else {
            int rr = r - B;
            x = stepw + (size_t)rr * M;
            o = out + O_STEP_PROBS + (size_t)rr * M;
        }
        float v[M];
        const float4* x4 = reinterpret_cast<const float4*>(x);
        #pragma unroll
        for (int q = 0; q < M / 4; q++) {
            float4 f = x4[q];
            v[4*q] = f.x; v[4*q+1] = f.y; v[4*q+2] = f.z; v[4*q+3] = f.w;
        }
        float mx = v[0];
        #pragma unroll
        for (int j = 1; j < M; j++) mx = fmaxf(mx, v[j]);
        float s = 0.f;
        #pragma unroll
        for (int j = 0; j < M; j++) { v[j] = __expf(v[j] - mx); s += v[j]; }
        float inv_s = 1.0f / s;
        float s2 = 0.f;
        #pragma unroll
        for (int j = 0; j < M; j++) {
            float pj   = v[j] * inv_s;
            float gate = 1.0f / (1.0f + __expf(-(pj - PRUNE_DELTA) / PRUNE_TAU));
            float pt   = pj * gate;
            v[j] = pt;
            s2 += pt;
        }
        float inv_s2 = 1.0f / (s2 + PRUNE_EPS);
        float s3 = 0.f;
        #pragma unroll
        for (int j = 0; j < M; j++) {
            float pn = v[j] * inv_s2 + PRUNE_EPS;
            v[j] = pn;
            s3 += pn;
        }
        float inv_s3 = 1.0f / s3;
        float4* o4 = reinterpret_cast<float4*>(o);
        #pragma unroll
        for (int q = 0; q < M / 4; q++)
            o4[q] = make_float4(v[4*q] * inv_s3, v[4*q+1] * inv_s3,
                                v[4*q+2] * inv_s3, v[4*q+3] * inv_s3);
        return;
    }

    // ---------------- chol + dense path ----------------
    int tile0 = (bid - SM_CTAS) * TILES_PER_CTA;

    // Phase 1: threads 0..(TILES_PER_CTA*T-1) -> (t = tid>>1, k = tid&1);
    // compute params, write mu / chol_step / loc, bake diag float4s in smem.
    if (tid < TILES_PER_CTA * T) {
        int k = tid & (TILES_PER_CTA - 1);
        int t = tid / TILES_PER_CTA;
        int tl = tile0 + k;            // tl = b*M + m
        int m = tl % M;
        int b = tl / M;
        int i = (b * T + t) * M + m;   // dense index (b,t,m)

        const float* p = ml + (size_t)i * 5;
        float mu_x = p[0];
        float mu_y = p[1];
        float sx   = sqrtf(expf(p[2]) + VAR_EPS);
        float sy   = sqrtf(expf(p[3]) + VAR_EPS);
        float rho  = tanhf(p[4]);

        float L11 = sx;
        float L21 = rho * sy;
        float L22 = sy * sqrtf(fmaxf(1.0f - rho * rho, 0.0f));

        // lane placement: diag col 2t occupies f4 lanes (2t&3, (2t&3)+1)
        bool hi = (t & 1);             // t odd -> values in .z/.w
        float4 ev = hi ? make_float4(0.f, 0.f, L11, 0.f)
                       : make_float4(L11, 0.f, 0.f, 0.f);
        float4 od = hi ? make_float4(0.f, 0.f, L21, L22)
                       : make_float4(L21, L22, 0.f, 0.f);
        DiagVal[k * ROWS_PER_TILE + 2 * t]     = ev;
        DiagVal[k * ROWS_PER_TILE + 2 * t + 1] = od;

        // mu [B,T,M,2]
        *reinterpret_cast<float2*>(out + O_MU + (size_t)i * 2) =
            make_float2(mu_x, mu_y);
        // chol_step [B,T,M,2,2] = [L11, 0, L21, L22]
        *reinterpret_cast<float4*>(out + O_CHOL_STEP + (size_t)i * 4) =
            make_float4(L11, 0.0f, L21, L22);
        // loc [B,M,2T]
        *reinterpret_cast<float2*>(out + O_LOC + (size_t)tl * TWO_T + 2 * t) =
            make_float2(mu_x, mu_y);
    }
    __syncthreads();

    // Phase 2: each thread owns f4 slots q = tid + 256*s, s in [0,4).
    // Diag slots (rare, tile-invariant) read baked values from smem; all
    // other slots store a constant-zero register directly.
    int  s_idx[4];      // smem row index within a tile block (diag only)
    bool s_diag[4];
    bool s_on[4];
    #pragma unroll
    for (int s = 0; s < 4; s++) {
        int q = tid + 256 * s;
        s_on[s] = (q < BLOCK_F4);
        int r  = q / 15;
        int c4 = q % 15;
        int t  = r >> 1;
        s_diag[s] = s_on[s] && (c4 == (t >> 1)) && (t < T);
        s_idx[s] = s_diag[s] ? r : 0;
    }

    float4* dst = reinterpret_cast<float4*>(out + O_CHOL_FULL) +
                  (size_t)tile0 * BLOCK_F4 + tid;
    const float4* diag_base = DiagVal;
    const float4 z4 = make_float4(0.f, 0.f, 0.f, 0.f);

    #pragma unroll
    for (int k = 0; k < TILES_PER_CTA; k++) {
        #pragma unroll
        for (int s = 0; s < 4; s++) {
            if (s_on[s]) {
                float4 v = z4;
                if (s_diag[s]) v = diag_base[s_idx[s]];
                __stcs(dst + 256 * s, v);
            }
        }
        diag_base += ROWS_PER_TILE;
        dst += BLOCK_F4;
    }
}

// ---------------------------------------------------------------------------
extern "C" void kernel_launch(void* const* d_in, const int* in_sizes, int n_in,
                              void* d_out, int out_size) {
    const float* ml    = (const float*)d_in[0];  // mixture_latent
    const float* trajw = (const float*)d_in[1];  // per_traj_weight
    const float* stepw = (const float*)d_in[2];  // per_step_weight
    float* out = (float*)d_out;

    mdn_fused<<<GRID_TOTAL, 256>>>(ml, trajw, stepw, out);
}